// round 1
// baseline (speedup 1.0000x reference)
#include <cuda_runtime.h>

#define NEG_INF (-1e30f)
#define BB 32
#define NN 256
#define KNB 20

// Scratch (device globals; no allocations allowed)
__device__ int   g_idx[BB*NN*KNB];      // top-20 neighbor indices per (b,n)
__device__ float g_H  [BB*NN*256];      // H[b][j][c] : per-point MLP output (c contiguous)
__device__ float g_Mt [BB*NN*256];      // Mt[b][n][c]: max over neighbors

// ---------------------------------------------------------------------------
// Kernel 1: kNN (top-20 of pairwise -||xi-xj||^2, ties -> lowest index)
// grid = 32 b * 8 row-slices = 256 blocks, 256 threads (8 warps * 4 rows)
// ---------------------------------------------------------------------------
__global__ __launch_bounds__(256) void knn_kernel(const float* __restrict__ x) {
    __shared__ float xs0[NN], xs1[NN], xs2[NN], xxs[NN];
    int b  = blockIdx.x >> 3;
    int rb = (blockIdx.x & 7) * 32;
    int tid = threadIdx.x;
    {
        float a0 = x[(b*NN + tid)*3 + 0];
        float a1 = x[(b*NN + tid)*3 + 1];
        float a2 = x[(b*NN + tid)*3 + 2];
        xs0[tid] = a0; xs1[tid] = a1; xs2[tid] = a2;
        xxs[tid] = a0*a0 + a1*a1 + a2*a2;
    }
    __syncthreads();
    int w = tid >> 5, lane = tid & 31;

    for (int r = 0; r < 4; r++) {
        int i = rb + w*4 + r;
        float xi0 = xs0[i], xi1 = xs1[i], xi2 = xs2[i], xxi = xxs[i];
        float d[8];
        #pragma unroll
        for (int t = 0; t < 8; t++) {
            int j = lane + 32*t;
            d[t] = 2.f*(xi0*xs0[j] + xi1*xs1[j] + xi2*xs2[j]) - xxi - xxs[j];
        }
        int out_base = (b*NN + i)*KNB;
        for (int kk = 0; kk < KNB; kk++) {
            // lane-local argmax (strict > keeps lowest j within lane)
            float bv = d[0]; int bj = lane;
            #pragma unroll
            for (int t = 1; t < 8; t++) {
                if (d[t] > bv) { bv = d[t]; bj = lane + 32*t; }
            }
            // warp butterfly argmax with tie -> lower index
            #pragma unroll
            for (int off = 16; off > 0; off >>= 1) {
                float ov = __shfl_xor_sync(0xffffffffu, bv, off);
                int   oj = __shfl_xor_sync(0xffffffffu, bj, off);
                if (ov > bv || (ov == bv && oj < bj)) { bv = ov; bj = oj; }
            }
            if (lane == 0) g_idx[out_base + kk] = bj;
            if ((bj & 31) == lane) {
                int wt = bj >> 5;
                #pragma unroll
                for (int t = 0; t < 8; t++) if (t == wt) d[t] = NEG_INF;
            }
        }
    }
}

// ---------------------------------------------------------------------------
// Kernel 2: per-point MLP  3 -> 64 -> 128 -> 256 (relu + folded-BN affine)
// grid = 128 blocks (64 rows each), 256 threads.
// SMEM: xs(192) H1s(4096) H2s(8192) W2T(8192 [c][o]) W3T(32768 [c][o])
// ---------------------------------------------------------------------------
#define MLP_SMEM_BYTES (53440*4)
__global__ __launch_bounds__(256) void mlp_kernel(
    const float* __restrict__ x,
    const float* __restrict__ w1, const float* __restrict__ s1, const float* __restrict__ t1,
    const float* __restrict__ w2, const float* __restrict__ s2, const float* __restrict__ t2,
    const float* __restrict__ w3, const float* __restrict__ s3, const float* __restrict__ t3)
{
    extern __shared__ float sm[];
    float* xs  = sm;            // 192
    float* H1s = sm + 192;      // 64*64
    float* H2s = sm + 4288;     // 64*128
    float* W2T = sm + 12480;    // [c][o] 64*128
    float* W3T = sm + 20672;    // [c][o] 128*256

    int tid = threadIdx.x;
    int row_base = blockIdx.x * 64;
    int b = row_base >> 8;
    int j_base = row_base & 255;

    if (tid < 192) xs[tid] = x[b*768 + j_base*3 + tid];
    for (int e = tid; e < 8192; e += 256)  { int o = e >> 6, c = e & 63;  W2T[c*128 + o] = w2[e]; }
    for (int e = tid; e < 32768; e += 256) { int o = e >> 7, c = e & 127; W3T[c*256 + o] = w3[e]; }
    __syncthreads();

    int w = tid >> 5, lane = tid & 31;
    int rb = w * 8;   // 8 rows per warp

    // ---- phase 1: h1 (each lane computes outputs lane, lane+32)
    {
        int o2 = lane + 32;
        float a0 = w1[lane*3], a1 = w1[lane*3+1], a2 = w1[lane*3+2];
        float b0 = w1[o2*3],   b1 = w1[o2*3+1],   b2 = w1[o2*3+2];
        float sa = s1[lane], ta = t1[lane], sb = s1[o2], tb = t1[o2];
        #pragma unroll
        for (int i = 0; i < 8; i++) {
            int row = rb + i;
            float x0 = xs[row*3], x1 = xs[row*3+1], x2 = xs[row*3+2];
            H1s[row*64 + lane]      = fmaxf(sa*(a0*x0 + a1*x1 + a2*x2) + ta, 0.f);
            H1s[row*64 + lane + 32] = fmaxf(sb*(b0*x0 + b1*x1 + b2*x2) + tb, 0.f);
        }
    }
    __syncthreads();

    // ---- phase 2: h2 = w2 @ h1 (lane outputs o = lane*4+k)
    {
        float acc[8][4];
        #pragma unroll
        for (int i = 0; i < 8; i++)
            #pragma unroll
            for (int k = 0; k < 4; k++) acc[i][k] = 0.f;
        for (int c = 0; c < 64; c++) {
            float4 wv = *(const float4*)&W2T[c*128 + lane*4];
            #pragma unroll
            for (int i = 0; i < 8; i++) {
                float h = H1s[(rb+i)*64 + c];
                acc[i][0] += h*wv.x; acc[i][1] += h*wv.y;
                acc[i][2] += h*wv.z; acc[i][3] += h*wv.w;
            }
        }
        float sv[4], tv[4];
        #pragma unroll
        for (int k = 0; k < 4; k++) { sv[k] = s2[lane*4+k]; tv[k] = t2[lane*4+k]; }
        #pragma unroll
        for (int i = 0; i < 8; i++)
            #pragma unroll
            for (int k = 0; k < 4; k++)
                H2s[(rb+i)*128 + lane*4 + k] = fmaxf(sv[k]*acc[i][k] + tv[k], 0.f);
    }
    __syncthreads();

    // ---- phase 3: h3 = w3 @ h2 (lane outputs o = lane*8+k), write g_H
    {
        float acc[8][8];
        #pragma unroll
        for (int i = 0; i < 8; i++)
            #pragma unroll
            for (int k = 0; k < 8; k++) acc[i][k] = 0.f;
        for (int c = 0; c < 128; c++) {
            float4 wa = *(const float4*)&W3T[c*256 + lane*8];
            float4 wb = *(const float4*)&W3T[c*256 + lane*8 + 4];
            #pragma unroll
            for (int i = 0; i < 8; i++) {
                float h = H2s[(rb+i)*128 + c];
                acc[i][0] += h*wa.x; acc[i][1] += h*wa.y;
                acc[i][2] += h*wa.z; acc[i][3] += h*wa.w;
                acc[i][4] += h*wb.x; acc[i][5] += h*wb.y;
                acc[i][6] += h*wb.z; acc[i][7] += h*wb.w;
            }
        }
        float sv[8], tv[8];
        #pragma unroll
        for (int k = 0; k < 8; k++) { sv[k] = s3[lane*8+k]; tv[k] = t3[lane*8+k]; }
        #pragma unroll
        for (int i = 0; i < 8; i++) {
            int row_g = row_base + rb + i;
            float4 oa, ob;
            oa.x = fmaxf(sv[0]*acc[i][0] + tv[0], 0.f);
            oa.y = fmaxf(sv[1]*acc[i][1] + tv[1], 0.f);
            oa.z = fmaxf(sv[2]*acc[i][2] + tv[2], 0.f);
            oa.w = fmaxf(sv[3]*acc[i][3] + tv[3], 0.f);
            ob.x = fmaxf(sv[4]*acc[i][4] + tv[4], 0.f);
            ob.y = fmaxf(sv[5]*acc[i][5] + tv[5], 0.f);
            ob.z = fmaxf(sv[6]*acc[i][6] + tv[6], 0.f);
            ob.w = fmaxf(sv[7]*acc[i][7] + tv[7], 0.f);
            *(float4*)&g_H[row_g*256 + lane*8]     = oa;
            *(float4*)&g_H[row_g*256 + lane*8 + 4] = ob;
        }
    }
}

// ---------------------------------------------------------------------------
// Kernel 3: neighbor gather-max.  grid = 32 b * 2 channel-halves = 64 blocks.
// Stage H[b][:, 128-ch half] (128KB) in SMEM; each warp handles 32 n.
// ---------------------------------------------------------------------------
#define MAX_SMEM_BYTES (32768*4)
__global__ __launch_bounds__(256) void max_kernel() {
    extern __shared__ float Hs[];   // [j][c_local] 256*128
    int b = blockIdx.x >> 1, half = blockIdx.x & 1;
    int tid = threadIdx.x;
    for (int e = tid; e < 8192; e += 256) {
        int j = e >> 5, q = e & 31;
        ((float4*)Hs)[e] = *(const float4*)(g_H + (b*256 + j)*256 + half*128 + q*4);
    }
    __syncthreads();
    int w = tid >> 5, lane = tid & 31;
    for (int t = 0; t < 32; t++) {
        int n = w*32 + t;
        int base = (b*NN + n)*KNB;
        float m0 = NEG_INF, m1 = NEG_INF, m2 = NEG_INF, m3 = NEG_INF;
        #pragma unroll
        for (int kk = 0; kk < KNB; kk++) {
            int j = g_idx[base + kk];
            int off = j*128 + lane;
            m0 = fmaxf(m0, Hs[off]);
            m1 = fmaxf(m1, Hs[off +  32]);
            m2 = fmaxf(m2, Hs[off +  64]);
            m3 = fmaxf(m3, Hs[off +  96]);
        }
        int ob = b*65536 + n*256 + half*128 + lane;
        g_Mt[ob] = m0; g_Mt[ob+32] = m1; g_Mt[ob+64] = m2; g_Mt[ob+96] = m3;
    }
}

// ---------------------------------------------------------------------------
// Kernel 4: fc1 (contract over n=256 -> 128, relu) + fc2 (128 -> 40)
// grid = 32 b * 4 channel-tiles(64) = 128 blocks, 256 threads.
// SMEM: Ms[n][c] stride 68 (17408 fl), W1T[n][o] stride 132 (33792 fl);
// after first stage done, Ms region is reused for Gs[c][o] (stride 133) + W2s.
// ---------------------------------------------------------------------------
#define FC_SMEM_BYTES (51200*4)
__global__ __launch_bounds__(256) void fc_kernel(
    const float* __restrict__ fc1_w, const float* __restrict__ fc1_b,
    const float* __restrict__ fc2_w, const float* __restrict__ fc2_b,
    float* __restrict__ out)
{
    extern __shared__ float sm[];
    float* Ms  = sm;            // [n][c] stride 68
    float* W1T = sm + 17408;    // [n][o] stride 132
    int tid = threadIdx.x;
    int b = blockIdx.x >> 2, ct = blockIdx.x & 3;

    for (int e = tid; e < 16384; e += 256) {
        int n = e >> 6, c = e & 63;
        Ms[n*68 + c] = g_Mt[b*65536 + n*256 + ct*64 + c];
    }
    for (int e = tid; e < 32768; e += 256) {
        int o = e >> 8, n = e & 255;
        W1T[n*132 + o] = fc1_w[e];
    }
    __syncthreads();

    int w = tid >> 5, lane = tid & 31;
    int oh = lane >> 4;
    int o_base = w*16 + oh*8;            // 8 warps * 2 halves * 8 = 128 o
    int c_base = (lane & 15) * 4;        // 16 groups * 4 = 64 c

    float acc[4][8];
    #pragma unroll
    for (int i = 0; i < 4; i++)
        #pragma unroll
        for (int k = 0; k < 8; k++) acc[i][k] = 0.f;

    for (int n = 0; n < 256; n++) {
        float4 mv = *(const float4*)&Ms[n*68 + c_base];
        float4 wa = *(const float4*)&W1T[n*132 + o_base];
        float4 wb = *(const float4*)&W1T[n*132 + o_base + 4];
        float m[4] = {mv.x, mv.y, mv.z, mv.w};
        float ww[8] = {wa.x, wa.y, wa.z, wa.w, wb.x, wb.y, wb.z, wb.w};
        #pragma unroll
        for (int i = 0; i < 4; i++)
            #pragma unroll
            for (int k = 0; k < 8; k++)
                acc[i][k] += m[i]*ww[k];
    }
    float b1v[8];
    #pragma unroll
    for (int k = 0; k < 8; k++) b1v[k] = fc1_b[o_base + k];

    __syncthreads();  // everyone done reading Ms/W1T

    float* Gs  = sm;            // [c][o] stride 133 (8512 fl, inside old Ms)
    float* W2s = sm + 8512;     // [q][o] stride 132 (5280 fl, inside old Ms)
    #pragma unroll
    for (int i = 0; i < 4; i++)
        #pragma unroll
        for (int k = 0; k < 8; k++)
            Gs[(c_base + i)*133 + o_base + k] = fmaxf(acc[i][k] + b1v[k], 0.f);
    for (int e = tid; e < 5120; e += 256) {
        int q = e >> 7, o = e & 127;
        W2s[q*132 + o] = fc2_w[e];
    }
    __syncthreads();

    // fc2: warp w -> q in [w*5, w*5+5); lane -> c = lane and lane+32
    float acc2[2][5];
    #pragma unroll
    for (int h = 0; h < 2; h++)
        #pragma unroll
        for (int q = 0; q < 5; q++) acc2[h][q] = 0.f;
    for (int o = 0; o < 128; o++) {
        float ga = Gs[lane*133 + o];
        float gb = Gs[(lane+32)*133 + o];
        #pragma unroll
        for (int q = 0; q < 5; q++) {
            float wv = W2s[(w*5 + q)*132 + o];
            acc2[0][q] += ga*wv;
            acc2[1][q] += gb*wv;
        }
    }
    #pragma unroll
    for (int h = 0; h < 2; h++) {
        int cg = ct*64 + lane + h*32;
        #pragma unroll
        for (int q = 0; q < 5; q++)
            out[(b*256 + cg)*40 + w*5 + q] = acc2[h][q] + fc2_b[w*5 + q];
    }
}

// ---------------------------------------------------------------------------
extern "C" void kernel_launch(void* const* d_in, const int* in_sizes, int n_in,
                              void* d_out, int out_size) {
    const float* x    = (const float*)d_in[0];
    const float* w1   = (const float*)d_in[1];
    const float* s1   = (const float*)d_in[2];
    const float* t1   = (const float*)d_in[3];
    const float* w2   = (const float*)d_in[4];
    const float* s2   = (const float*)d_in[5];
    const float* t2   = (const float*)d_in[6];
    const float* w3   = (const float*)d_in[7];
    const float* s3   = (const float*)d_in[8];
    const float* t3   = (const float*)d_in[9];
    const float* fc1w = (const float*)d_in[10];
    const float* fc1b = (const float*)d_in[11];
    const float* fc2w = (const float*)d_in[12];
    const float* fc2b = (const float*)d_in[13];
    float* out = (float*)d_out;

    cudaFuncSetAttribute(mlp_kernel, cudaFuncAttributeMaxDynamicSharedMemorySize, MLP_SMEM_BYTES);
    cudaFuncSetAttribute(max_kernel, cudaFuncAttributeMaxDynamicSharedMemorySize, MAX_SMEM_BYTES);
    cudaFuncSetAttribute(fc_kernel,  cudaFuncAttributeMaxDynamicSharedMemorySize, FC_SMEM_BYTES);

    knn_kernel<<<256, 256>>>(x);
    mlp_kernel<<<128, 256, MLP_SMEM_BYTES>>>(x, w1, s1, t1, w2, s2, t2, w3, s3, t3);
    max_kernel<<<64, 256, MAX_SMEM_BYTES>>>();
    fc_kernel<<<128, 256, FC_SMEM_BYTES>>>(fc1w, fc1b, fc2w, fc2b, out);
}

// round 2
// speedup vs baseline: 1.4109x; 1.4109x over previous
#include <cuda_runtime.h>

#define NEG_INF (-1e30f)
#define BB 32
#define NN 256
#define KNB 20

// Scratch (device globals; no allocations allowed)
__device__ int   g_idx[BB*NN*KNB];
__device__ float g_H  [BB*NN*256];
__device__ float g_Mt [BB*NN*256];
__device__ float g_H2 [BB*NN*128];
__device__ float g_w2T[64*128];
__device__ float g_w3T[128*256];
__device__ float g_w1T[256*128];

__global__ __launch_bounds__(256) void transpose_kernel(
    const float* __restrict__ w2, const float* __restrict__ w3,
    const float* __restrict__ fc1w)
{
    int tid = blockIdx.x*256 + threadIdx.x;
    if (tid < 8192) { int c = tid >> 7, o = tid & 127; g_w2T[tid] = w2[o*64 + c]; }
    int t2 = tid - 8192;
    if (t2 >= 0 && t2 < 32768) { int c = t2 >> 8, o = t2 & 255; g_w3T[t2] = w3[o*128 + c]; }
    int t3 = tid - 40960;
    if (t3 >= 0 && t3 < 32768) { int n = t3 >> 7, o = t3 & 127; g_w1T[t3] = fc1w[o*256 + n]; }
}

__global__ __launch_bounds__(256) void knn_kernel(const float* __restrict__ x) {
    __shared__ float xs0[NN], xs1[NN], xs2[NN], xxs[NN];
    int b      = blockIdx.x >> 5;
    int n_base = (blockIdx.x & 31) * 8;
    int tid = threadIdx.x;
    {
        float a0 = x[(b*NN + tid)*3 + 0];
        float a1 = x[(b*NN + tid)*3 + 1];
        float a2 = x[(b*NN + tid)*3 + 2];
        xs0[tid] = a0; xs1[tid] = a1; xs2[tid] = a2;
        xxs[tid] = a0*a0 + a1*a1 + a2*a2;
    }
    __syncthreads();
    int w = tid >> 5, lane = tid & 31;
    int i = n_base + w;

    float xi0 = xs0[i], xi1 = xs1[i], xi2 = xs2[i], xxi = xxs[i];
    unsigned m[8];
    #pragma unroll
    for (int t = 0; t < 8; t++) {
        int j = lane + 32*t;
        float dv = 2.f*(xi0*xs0[j] + xi1*xs1[j] + xi2*xs2[j]) - xxi - xxs[j];
        unsigned u = __float_as_uint(dv);
        m[t] = u ^ (unsigned)(((int)u >> 31) | 0x80000000);
    }

    int myj = 0;
    #pragma unroll 4
    for (int kk = 0; kk < KNB; kk++) {
        unsigned bv = m[0]; int bj = lane;
        #pragma unroll
        for (int t = 1; t < 8; t++)
            if (m[t] > bv) { bv = m[t]; bj = lane + 32*t; }
        unsigned vmax = __reduce_max_sync(0xffffffffu, bv);
        unsigned cand = (bv == vmax) ? (unsigned)bj : 0x7fffffffu;
        int jwin = (int)__reduce_min_sync(0xffffffffu, cand);
        if (lane == kk) myj = jwin;
        if ((jwin & 31) == lane) {
            int t = jwin >> 5;
            #pragma unroll
            for (int tt = 0; tt < 8; tt++) if (tt == t) m[tt] = 0u;
        }
    }
    if (lane < KNB) g_idx[(b*NN + i)*KNB + lane] = myj;
}

#define MLP12_SMEM ((96 + 2048 + 8192)*4)
__global__ __launch_bounds__(256) void mlp12_kernel(
    const float* __restrict__ x,
    const float* __restrict__ w1, const float* __restrict__ s1, const float* __restrict__ t1,
    const float* __restrict__ s2, const float* __restrict__ t2)
{
    extern __shared__ float sm[];
    float* xs   = sm;
    float* H1s  = sm + 96;
    float* W2Ts = sm + 2144;

    int tid = threadIdx.x;
    int row_base = blockIdx.x * 32;
    int b = row_base >> 8;
    int j0 = row_base & 255;

    if (tid < 96) xs[tid] = x[b*768 + j0*3 + tid];
    for (int e = tid; e < 2048; e += 256)
        ((float4*)W2Ts)[e] = ((const float4*)g_w2T)[e];
    __syncthreads();

    int w = tid >> 5, lane = tid & 31;
    int rb = w * 4;

    {
        int o2 = lane + 32;
        float a0 = w1[lane*3], a1 = w1[lane*3+1], a2 = w1[lane*3+2];
        float b0 = w1[o2*3],   b1 = w1[o2*3+1],   b2 = w1[o2*3+2];
        float sa = s1[lane], ta = t1[lane], sb = s1[o2], tb = t1[o2];
        #pragma unroll
        for (int i = 0; i < 4; i++) {
            int row = rb + i;
            float x0 = xs[row*3], x1 = xs[row*3+1], x2 = xs[row*3+2];
            H1s[row*64 + lane]      = fmaxf(sa*(a0*x0 + a1*x1 + a2*x2) + ta, 0.f);
            H1s[row*64 + lane + 32] = fmaxf(sb*(b0*x0 + b1*x1 + b2*x2) + tb, 0.f);
        }
    }
    __syncthreads();

    float acc[4][4];
    #pragma unroll
    for (int i = 0; i < 4; i++)
        #pragma unroll
        for (int k = 0; k < 4; k++) acc[i][k] = 0.f;
    #pragma unroll 8
    for (int c = 0; c < 64; c++) {
        float4 wv = *(const float4*)&W2Ts[c*128 + lane*4];
        #pragma unroll
        for (int i = 0; i < 4; i++) {
            float h = H1s[(rb+i)*64 + c];
            acc[i][0] += h*wv.x; acc[i][1] += h*wv.y;
            acc[i][2] += h*wv.z; acc[i][3] += h*wv.w;
        }
    }
    float sv[4], tv[4];
    #pragma unroll
    for (int k = 0; k < 4; k++) { sv[k] = s2[lane*4+k]; tv[k] = t2[lane*4+k]; }
    #pragma unroll
    for (int i = 0; i < 4; i++) {
        float4 o;
        o.x = fmaxf(sv[0]*acc[i][0] + tv[0], 0.f);
        o.y = fmaxf(sv[1]*acc[i][1] + tv[1], 0.f);
        o.z = fmaxf(sv[2]*acc[i][2] + tv[2], 0.f);
        o.w = fmaxf(sv[3]*acc[i][3] + tv[3], 0.f);
        *(float4*)&g_H2[(row_base + rb + i)*128 + lane*4] = o;
    }
}

#define MLP3_SMEM ((8192 + 16384)*4)
__global__ __launch_bounds__(256) void mlp3_kernel(
    const float* __restrict__ s3, const float* __restrict__ t3)
{
    extern __shared__ float sm[];
    float* H2s  = sm;
    float* W3Ts = sm + 8192;

    int bid = blockIdx.x;
    int row0 = (bid >> 1) * 64;
    int oh = bid & 1;
    int tid = threadIdx.x;

    for (int e = tid; e < 2048; e += 256)
        ((float4*)H2s)[e] = ((const float4*)(g_H2 + row0*128))[e];
    for (int e = tid; e < 4096; e += 256) {
        int c = e >> 5, q = e & 31;
        ((float4*)W3Ts)[e] = *(const float4*)(g_w3T + c*256 + oh*128 + q*4);
    }
    __syncthreads();

    int w = tid >> 5, lane = tid & 31;
    int rb = w*8 + (lane >> 4)*4;
    int ob = (lane & 15)*8;

    float acc[4][8];
    #pragma unroll
    for (int i = 0; i < 4; i++)
        #pragma unroll
        for (int k = 0; k < 8; k++) acc[i][k] = 0.f;

    #pragma unroll 4
    for (int c = 0; c < 128; c++) {
        float4 wa = *(const float4*)&W3Ts[c*128 + ob];
        float4 wb = *(const float4*)&W3Ts[c*128 + ob + 4];
        #pragma unroll
        for (int i = 0; i < 4; i++) {
            float h = H2s[(rb+i)*128 + c];
            acc[i][0] += h*wa.x; acc[i][1] += h*wa.y;
            acc[i][2] += h*wa.z; acc[i][3] += h*wa.w;
            acc[i][4] += h*wb.x; acc[i][5] += h*wb.y;
            acc[i][6] += h*wb.z; acc[i][7] += h*wb.w;
        }
    }
    float sv[8], tv[8];
    #pragma unroll
    for (int k = 0; k < 8; k++) { sv[k] = s3[oh*128 + ob + k]; tv[k] = t3[oh*128 + ob + k]; }
    #pragma unroll
    for (int i = 0; i < 4; i++) {
        int row = row0 + rb + i;
        float4 oa, obv;
        oa.x  = fmaxf(sv[0]*acc[i][0] + tv[0], 0.f);
        oa.y  = fmaxf(sv[1]*acc[i][1] + tv[1], 0.f);
        oa.z  = fmaxf(sv[2]*acc[i][2] + tv[2], 0.f);
        oa.w  = fmaxf(sv[3]*acc[i][3] + tv[3], 0.f);
        obv.x = fmaxf(sv[4]*acc[i][4] + tv[4], 0.f);
        obv.y = fmaxf(sv[5]*acc[i][5] + tv[5], 0.f);
        obv.z = fmaxf(sv[6]*acc[i][6] + tv[6], 0.f);
        obv.w = fmaxf(sv[7]*acc[i][7] + tv[7], 0.f);
        *(float4*)&g_H[row*256 + oh*128 + ob]     = oa;
        *(float4*)&g_H[row*256 + oh*128 + ob + 4] = obv;
    }
}

#define MAX_SMEM (16384*4)
__global__ __launch_bounds__(256) void max_kernel() {
    extern __shared__ float Hs[];
    int b = blockIdx.x >> 2, qt = blockIdx.x & 3;
    int tid = threadIdx.x;
    for (int e = tid; e < 4096; e += 256) {
        int j = e >> 4, q = e & 15;
        ((float4*)Hs)[e] = *(const float4*)(g_H + (b*256 + j)*256 + qt*64 + q*4);
    }
    __syncthreads();
    int w = tid >> 5, lane = tid & 31;
    for (int t = 0; t < 32; t++) {
        int n = w*32 + t;
        const int4* ip = (const int4*)(g_idx + (b*NN + n)*KNB);
        float m0 = NEG_INF, m1 = NEG_INF;
        #pragma unroll
        for (int q = 0; q < 5; q++) {
            int4 v = ip[q];
            m0 = fmaxf(m0, Hs[v.x*64 + lane]); m1 = fmaxf(m1, Hs[v.x*64 + lane + 32]);
            m0 = fmaxf(m0, Hs[v.y*64 + lane]); m1 = fmaxf(m1, Hs[v.y*64 + lane + 32]);
            m0 = fmaxf(m0, Hs[v.z*64 + lane]); m1 = fmaxf(m1, Hs[v.z*64 + lane + 32]);
            m0 = fmaxf(m0, Hs[v.w*64 + lane]); m1 = fmaxf(m1, Hs[v.w*64 + lane + 32]);
        }
        int ob = b*65536 + n*256 + qt*64 + lane;
        g_Mt[ob] = m0; g_Mt[ob + 32] = m1;
    }
}

#define FC_SMEM ((16384 + 32768 + 5120)*4)
__global__ __launch_bounds__(512) void fc_kernel(
    const float* __restrict__ fc1_b,
    const float* __restrict__ fc2_w, const float* __restrict__ fc2_b,
    float* __restrict__ out)
{
    extern __shared__ float sm[];
    float* Ms   = sm;
    float* W1Ts = sm + 16384;
    float* W2s  = sm + 49152;
    int b = blockIdx.x >> 2, ct = blockIdx.x & 3;
    int tid = threadIdx.x;

    for (int e = tid; e < 4096; e += 512) {
        int n = e >> 4, q = e & 15;
        ((float4*)Ms)[e] = *(const float4*)(g_Mt + b*65536 + n*256 + ct*64 + q*4);
    }
    for (int e = tid; e < 8192; e += 512)
        ((float4*)W1Ts)[e] = ((const float4*)g_w1T)[e];
    for (int e = tid; e < 1280; e += 512)
        ((float4*)W2s)[e] = ((const float4*)fc2_w)[e];
    __syncthreads();

    int w = tid >> 5, lane = tid & 31;
    int half = w >> 3, w8 = w & 7;
    int o_base = w8*16 + (lane >> 4)*8;
    int c_base = (lane & 15)*4;

    float acc[4][8];
    #pragma unroll
    for (int i = 0; i < 4; i++)
        #pragma unroll
        for (int k = 0; k < 8; k++) acc[i][k] = 0.f;

    int n0 = half*128;
    #pragma unroll 4
    for (int n = n0; n < n0 + 128; n++) {
        float4 mv = *(const float4*)&Ms[n*64 + c_base];
        float4 wa = *(const float4*)&W1Ts[n*128 + o_base];
        float4 wb = *(const float4*)&W1Ts[n*128 + o_base + 4];
        float mm[4] = {mv.x, mv.y, mv.z, mv.w};
        float ww[8] = {wa.x, wa.y, wa.z, wa.w, wb.x, wb.y, wb.z, wb.w};
        #pragma unroll
        for (int i = 0; i < 4; i++)
            #pragma unroll
            for (int k = 0; k < 8; k++)
                acc[i][k] += mm[i]*ww[k];
    }
    __syncthreads();

    float* Rs = sm;
    float* Gs = sm + 8320;
    if (half == 1) {
        #pragma unroll
        for (int i = 0; i < 4; i++)
            #pragma unroll
            for (int k = 0; k < 8; k++)
                Rs[(c_base + i)*129 + o_base + k] = acc[i][k];
    }
    __syncthreads();
    if (half == 0) {
        float b1v[8];
        #pragma unroll
        for (int k = 0; k < 8; k++) b1v[k] = fc1_b[o_base + k];
        #pragma unroll
        for (int i = 0; i < 4; i++)
            #pragma unroll
            for (int k = 0; k < 8; k++)
                Gs[(c_base + i)*129 + o_base + k] =
                    fmaxf(acc[i][k] + Rs[(c_base + i)*129 + o_base + k] + b1v[k], 0.f);
    }
    __syncthreads();

    if (w < 8) {
        float acc2[2][5];
        #pragma unroll
        for (int h = 0; h < 2; h++)
            #pragma unroll
            for (int q = 0; q < 5; q++) acc2[h][q] = 0.f;
        #pragma unroll 4
        for (int o = 0; o < 128; o++) {
            float ga = Gs[lane*129 + o];
            float gb = Gs[(lane + 32)*129 + o];
            #pragma unroll
            for (int q = 0; q < 5; q++) {
                float wv = W2s[(w*5 + q)*128 + o];
                acc2[0][q] += ga*wv;
                acc2[1][q] += gb*wv;
            }
        }
        #pragma unroll
        for (int h = 0; h < 2; h++) {
            int cg = ct*64 + lane + h*32;
            #pragma unroll
            for (int q = 0; q < 5; q++)
                out[(b*256 + cg)*40 + w*5 + q] = acc2[h][q] + fc2_b[w*5 + q];
        }
    }
}

extern "C" void kernel_launch(void* const* d_in, const int* in_sizes, int n_in,
                              void* d_out, int out_size) {
    const float* x    = (const float*)d_in[0];
    const float* w1   = (const float*)d_in[1];
    const float* s1   = (const float*)d_in[2];
    const float* t1   = (const float*)d_in[3];
    const float* w2   = (const float*)d_in[4];
    const float* s2   = (const float*)d_in[5];
    const float* t2   = (const float*)d_in[6];
    const float* w3   = (const float*)d_in[7];
    const float* s3   = (const float*)d_in[8];
    const float* t3   = (const float*)d_in[9];
    const float* fc1w = (const float*)d_in[10];
    const float* fc1b = (const float*)d_in[11];
    const float* fc2w = (const float*)d_in[12];
    const float* fc2b = (const float*)d_in[13];
    float* out = (float*)d_out;

    cudaFuncSetAttribute(mlp12_kernel, cudaFuncAttributeMaxDynamicSharedMemorySize, MLP12_SMEM);
    cudaFuncSetAttribute(mlp3_kernel,  cudaFuncAttributeMaxDynamicSharedMemorySize, MLP3_SMEM);
    cudaFuncSetAttribute(max_kernel,   cudaFuncAttributeMaxDynamicSharedMemorySize, MAX_SMEM);
    cudaFuncSetAttribute(fc_kernel,    cudaFuncAttributeMaxDynamicSharedMemorySize, FC_SMEM);

    transpose_kernel<<<288, 256>>>(w2, w3, fc1w);
    knn_kernel<<<1024, 256>>>(x);
    mlp12_kernel<<<256, 256, MLP12_SMEM>>>(x, w1, s1, t1, s2, t2);
    mlp3_kernel<<<256, 256, MLP3_SMEM>>>(s3, t3);
    max_kernel<<<128, 256, MAX_SMEM>>>();
    fc_kernel<<<128, 512, FC_SMEM>>>(fc1b, fc2w, fc2b, out);
}